// round 14
// baseline (speedup 1.0000x reference)
#include <cuda_runtime.h>
#include <cuda_fp16.h>
#include <cstdint>

#define M_DIM    64
#define K_DIM    4096
#define N_DIM    11008
#define NGROUPS  32
#define KC       64                    // k per chunk
#define SPLIT    8                     // K-split factor
#define CPS      (K_DIM / KC / SPLIT)  // chunks per split = 8
#define NTILE    64                    // n columns per CTA
#define NTB      (N_DIM / NTILE)       // 172 n-tiles
#define NTHREADS 128

__device__ float4 g_part4[SPLIT * NTB * 1024];   // 22.5 MB flat split-K partials
__device__ int    g_cnt[NTB];                    // arrival counters (0 after every run)

__device__ __forceinline__ uint32_t smem_u32(const void* p) {
    uint32_t a;
    asm("{ .reg .u64 t; cvta.to.shared.u64 t, %1; cvt.u32.u64 %0, t; }" : "=r"(a) : "l"(p));
    return a;
}

// Load 8 consecutive fp32 x values, convert to permuted fp16 pairs
// (k, k+4) -> one half2, matching the dequant LOP3 nibble extraction.
__device__ __forceinline__ uint4 load_cvt_x(const float* __restrict__ p) {
    const float4 lo = *reinterpret_cast<const float4*>(p);
    const float4 hi = *reinterpret_cast<const float4*>(p + 4);
    __half2 h0 = __floats2half2_rn(lo.x, hi.x);
    __half2 h1 = __floats2half2_rn(lo.y, hi.y);
    __half2 h2 = __floats2half2_rn(lo.z, hi.z);
    __half2 h3 = __floats2half2_rn(lo.w, hi.w);
    uint4 r;
    r.x = *reinterpret_cast<uint32_t*>(&h0);
    r.y = *reinterpret_cast<uint32_t*>(&h1);
    r.z = *reinterpret_cast<uint32_t*>(&h2);
    r.w = *reinterpret_cast<uint32_t*>(&h3);
    return r;
}

__device__ __forceinline__ void dequant_word(unsigned word, uint32_t zz, uint32_t s2,
                                             uint32_t sts) {
    uint32_t r[4];
#pragma unroll
    for (int j = 0; j < 4; j++) {
        uint32_t p;
        asm("lop3.b32 %0, %1, 0x000F000F, 0x64006400, 0xEA;" : "=r"(p) : "r"(word >> (4 * j)));
        asm("sub.rn.f16x2 %0, %0, %1;" : "+r"(p) : "r"(zz));
        asm("mul.rn.f16x2 %0, %1, %2;" : "=r"(r[j]) : "r"(p), "r"(s2));
    }
    asm volatile("st.shared.v4.b32 [%0], {%1,%2,%3,%4};"
        :: "r"(sts), "r"(r[0]), "r"(r[1]), "r"(r[2]), "r"(r[3]) : "memory");
}

__device__ __forceinline__ void sts128(uint32_t addr, uint4 v) {
    asm volatile("st.shared.v4.b32 [%0], {%1,%2,%3,%4};"
        :: "r"(addr), "r"(v.x), "r"(v.y), "r"(v.z), "r"(v.w) : "memory");
}

// ---------------------------------------------------------------------------
// Single fused kernel: int4-dequant GEMM (mma.sync m16n8k16) + inline x
// fp32->fp16 staging + last-CTA split-K reduction.
// CTA: 64m x 64n x K/8, 4 warps (2m x 2n), warp tile 32m x 32n.
// Grid (172, 8): blockIdx.x = n-tile, blockIdx.y = k-split.
// SMEM swizzle: 16B group kg at row r lives at  r*128 + ((kg ^ (r&7))*16).
// ---------------------------------------------------------------------------
__global__ __launch_bounds__(NTHREADS, 4)
void gptq_fused_kernel(const float* __restrict__ x,        // [M, K] fp32
                       const int*   __restrict__ qweight,  // [K/8, N]
                       const int*   __restrict__ qzeros,   // [NGROUPS, N/8]
                       const float* __restrict__ scales,   // [NGROUPS, N]
                       const float* __restrict__ bias,     // [N]
                       float*       __restrict__ out)      // [M, N]
{
    __shared__ __align__(16) __half a_s[2][M_DIM * KC];   // x tile   2 x 8 KB
    __shared__ __align__(16) __half w_s[2][NTILE * KC];   // W tile   2 x 8 KB

    const int tid   = threadIdx.x;
    const int lane  = tid & 31;
    const int wid   = tid >> 5;
    const int nblk  = blockIdx.x * NTILE;
    const int split = blockIdx.y;
    const int cbase = split * CPS;

    const uint32_t a_base = smem_u32(a_s);
    const uint32_t w_base = smem_u32(w_s);

    // ---- dequant assignment: 4 qweight words / thread / chunk (one column)
    const int dq_n  = tid & 63;             // local n
    const int kwh   = tid >> 6;             // 0/1 -> words 0-3 or 4-7
    const int dq_gn = nblk + dq_n;
    uint32_t dq_sts[4];
#pragma unroll
    for (int j = 0; j < 4; j++)
        dq_sts[j] = w_base + (uint32_t)(dq_n * 128 + (((kwh * 4 + j) ^ (dq_n & 7)) * 16));

    // ---- x stage assignment: four 16B groups / thread / chunk (load+convert)
    uint32_t xs_dst[4];
    const float* xs_src[4];
#pragma unroll
    for (int i = 0; i < 4; i++) {
        const int v  = tid + i * NTHREADS;   // 0..511
        const int m  = v >> 3;
        const int kg = v & 7;
        xs_dst[i] = a_base + (uint32_t)(m * 128 + ((kg ^ (m & 7)) * 16));
        xs_src[i] = x + m * K_DIM + cbase * KC + kg * 8;
    }

    // ---- compute assignment: warp (wm, wn), tile 32m x 32n
    const int wm = wid & 1, wn = wid >> 1;
    const int m0  = wm * 32;
    const int nw0 = wn * 32;
    const int lrow_a = m0  + (lane & 15);
    const int lrow_b = nw0 + (lane & 15);
    const int khalf  = lane >> 4;            // 0: k+0, 1: k+8
    const uint32_t ldm_a0 = a_base + (uint32_t)(lrow_a * 128);
    const uint32_t ldm_a1 = ldm_a0 + 16u * 128u;     // rows +16 (same swizzle phase)
    const uint32_t ldm_b0 = w_base + (uint32_t)(lrow_b * 128);
    const uint32_t ldm_b1 = ldm_b0 + 16u * 128u;
    const int swz_a = lrow_a & 7, swz_b = lrow_b & 7;

    float acc[2][2][2][4] = {};   // [mi][nj][n8][4]

    // ================= stage chunk 0 of this split =================
    {
        uint4 xv[4];
#pragma unroll
        for (int i = 0; i < 4; i++) xv[i] = load_cvt_x(xs_src[i]);
#pragma unroll
        for (int i = 0; i < 4; i++) sts128(xs_dst[i], xv[i]);

        const int c0 = cbase;
        const int g  = c0 >> 1;
        unsigned w[4];
#pragma unroll
        for (int j = 0; j < 4; j++)
            w[j] = (unsigned)qweight[(c0 * 8 + kwh * 4 + j) * N_DIM + dq_gn];
        const float    s  = scales[g * N_DIM + dq_gn];
        const int      zw = qzeros[g * (N_DIM / 8) + (dq_gn >> 3)];
        const int      z  = ((zw >> ((dq_gn & 7) * 4)) & 15) + 1;
        const uint32_t zz = 0x64006400u + (uint32_t)z * 0x00010001u;
        const uint16_t hb = __half_as_ushort(__float2half_rn(s));
        const uint32_t s2 = ((uint32_t)hb << 16) | hb;
#pragma unroll
        for (int j = 0; j < 4; j++) dequant_word(w[j], zz, s2, dq_sts[j]);
    }
    __syncthreads();

    // ================= main loop =================
#pragma unroll 1
    for (int lc = 0; lc < CPS; lc++) {
        const uint32_t aoff  = (uint32_t)((lc & 1) * (M_DIM * KC * 2));
        const uint32_t woff  = (uint32_t)((lc & 1) * (NTILE * KC * 2));
        const uint32_t naoff = (uint32_t)(((lc + 1) & 1) * (M_DIM * KC * 2));
        const uint32_t nwoff = (uint32_t)(((lc + 1) & 1) * (NTILE * KC * 2));

        unsigned nwd[4]; uint32_t nzz = 0, ns2 = 0;
        uint4 nxv[4];
        const bool has_next = (lc + 1 < CPS);
        if (has_next) {
            const int nc = cbase + lc + 1;
#pragma unroll
            for (int i = 0; i < 4; i++) nxv[i] = load_cvt_x(xs_src[i] + (lc + 1) * KC);

            const int g = nc >> 1;
#pragma unroll
            for (int j = 0; j < 4; j++)
                nwd[j] = (unsigned)qweight[(nc * 8 + kwh * 4 + j) * N_DIM + dq_gn];
            const float s  = scales[g * N_DIM + dq_gn];
            const int   zw = qzeros[g * (N_DIM / 8) + (dq_gn >> 3)];
            const int   z  = ((zw >> ((dq_gn & 7) * 4)) & 15) + 1;
            nzz = 0x64006400u + (uint32_t)z * 0x00010001u;
            const uint16_t hb = __half_as_ushort(__float2half_rn(s));
            ns2 = ((uint32_t)hb << 16) | hb;
        }

        // ---- compute chunk: 4 k-tiles of 16; per kt: 4 LDSM, 8 MMA
#pragma unroll
        for (int kt = 0; kt < 4; kt++) {
            const int kg = 2 * kt + khalf;
            uint32_t a0[4], a1[4], b0[4], b1[4];
            asm volatile("ldmatrix.sync.aligned.m8n8.x4.shared.b16 {%0,%1,%2,%3}, [%4];"
                : "=r"(a0[0]), "=r"(a0[1]), "=r"(a0[2]), "=r"(a0[3])
                : "r"(ldm_a0 + aoff + (uint32_t)((kg ^ swz_a) * 16)));
            asm volatile("ldmatrix.sync.aligned.m8n8.x4.shared.b16 {%0,%1,%2,%3}, [%4];"
                : "=r"(a1[0]), "=r"(a1[1]), "=r"(a1[2]), "=r"(a1[3])
                : "r"(ldm_a1 + aoff + (uint32_t)((kg ^ swz_a) * 16)));
            asm volatile("ldmatrix.sync.aligned.m8n8.x4.shared.b16 {%0,%1,%2,%3}, [%4];"
                : "=r"(b0[0]), "=r"(b0[1]), "=r"(b0[2]), "=r"(b0[3])
                : "r"(ldm_b0 + woff + (uint32_t)((kg ^ swz_b) * 16)));
            asm volatile("ldmatrix.sync.aligned.m8n8.x4.shared.b16 {%0,%1,%2,%3}, [%4];"
                : "=r"(b1[0]), "=r"(b1[1]), "=r"(b1[2]), "=r"(b1[3])
                : "r"(ldm_b1 + woff + (uint32_t)((kg ^ swz_b) * 16)));
#pragma unroll
            for (int mi = 0; mi < 2; mi++) {
                const uint32_t* a = mi ? a1 : a0;
#pragma unroll
                for (int nj = 0; nj < 2; nj++) {
                    const uint32_t* b = nj ? b1 : b0;
                    asm volatile(
                        "mma.sync.aligned.m16n8k16.row.col.f32.f16.f16.f32 "
                        "{%0,%1,%2,%3}, {%4,%5,%6,%7}, {%8,%9}, {%0,%1,%2,%3};"
                        : "+f"(acc[mi][nj][0][0]), "+f"(acc[mi][nj][0][1]),
                          "+f"(acc[mi][nj][0][2]), "+f"(acc[mi][nj][0][3])
                        : "r"(a[0]), "r"(a[1]), "r"(a[2]), "r"(a[3]), "r"(b[0]), "r"(b[2]));
                    asm volatile(
                        "mma.sync.aligned.m16n8k16.row.col.f32.f16.f16.f32 "
                        "{%0,%1,%2,%3}, {%4,%5,%6,%7}, {%8,%9}, {%0,%1,%2,%3};"
                        : "+f"(acc[mi][nj][1][0]), "+f"(acc[mi][nj][1][1]),
                          "+f"(acc[mi][nj][1][2]), "+f"(acc[mi][nj][1][3])
                        : "r"(a[0]), "r"(a[1]), "r"(a[2]), "r"(a[3]), "r"(b[1]), "r"(b[3]));
                }
            }
        }

        if (has_next) {
            dequant_word(nwd[0], nzz, ns2, dq_sts[0] + nwoff);
            dequant_word(nwd[1], nzz, ns2, dq_sts[1] + nwoff);
            dequant_word(nwd[2], nzz, ns2, dq_sts[2] + nwoff);
            dequant_word(nwd[3], nzz, ns2, dq_sts[3] + nwoff);
#pragma unroll
            for (int i = 0; i < 4; i++) sts128(xs_dst[i] + naoff, nxv[i]);
        }
        __syncthreads();
    }

    // ====== epilogue: flat coalesced partial dump (16KB contiguous / CTA) ======
    // float4 index j*128 + tid,  j = mi*4 + nj*2 + t. Reducer owns the map.
    {
        float4* part = g_part4 + ((size_t)split * NTB + blockIdx.x) * 1024;
#pragma unroll
        for (int mi = 0; mi < 2; mi++)
#pragma unroll
            for (int nj = 0; nj < 2; nj++)
#pragma unroll
                for (int t = 0; t < 2; t++) {
                    const int j = mi * 4 + nj * 2 + t;
                    part[j * 128 + tid] = make_float4(acc[mi][nj][t][0], acc[mi][nj][t][1],
                                                      acc[mi][nj][t][2], acc[mi][nj][t][3]);
                }
    }

    // ====== fused split-K reduction: last-arriving CTA per n-tile ======
    __threadfence();
    __syncthreads();
    __shared__ int is_last;
    if (tid == 0) {
        const int old = atomicAdd(&g_cnt[blockIdx.x], 1);
        is_last = (old == SPLIT - 1);
    }
    __syncthreads();
    if (!is_last) return;

    // sum the 8 partials into smem (reuse a_s: exactly 16 KB = 1024 float4)
    float4* sm = reinterpret_cast<float4*>(a_s);
    {
        const float4* base = g_part4 + (size_t)blockIdx.x * 1024;
#pragma unroll
        for (int ii = 0; ii < 8; ii++) {
            const int idx = ii * NTHREADS + tid;
            float4 s = base[idx];
#pragma unroll
            for (int p = 1; p < SPLIT; p++) {
                const float4 v = base[(size_t)p * (NTB * 1024) + idx];
                s.x += v.x; s.y += v.y; s.z += v.z; s.w += v.w;
            }
            sm[idx] = s;
        }
    }
    __syncthreads();

    // inverse fragment map (bench-verified in R13) + bias + store
    {
        const float* smf = reinterpret_cast<const float*>(sm);
#pragma unroll
        for (int iter = 0; iter < 32; iter++) {
            const int m = iter * 2 + (tid >> 6);
            const int c = tid & 63;
            const int ln = ((m & 7) << 2) | ((c >> 1) & 3);
            const int wd = ((m >> 5) & 1) | (((c >> 5) & 1) << 1);
            const int j  = (((m >> 4) & 1) << 2) | (((c >> 4) & 1) << 1) | ((c >> 3) & 1);
            const int e  = (((m >> 3) & 1) << 1) | (c & 1);
            const float v = smf[(((j * 128) + (wd * 32 + ln)) << 2) | e];
            const int n   = nblk + c;
            out[(size_t)m * N_DIM + n] = v + bias[n];
        }
    }

    if (tid == 0) g_cnt[blockIdx.x] = 0;   // reset for next graph replay
}

// ---------------------------------------------------------------------------
extern "C" void kernel_launch(void* const* d_in, const int* in_sizes, int n_in,
                              void* d_out, int out_size) {
    const float* x       = (const float*)d_in[0];
    const int*   qweight = (const int*)  d_in[1];
    const int*   qzeros  = (const int*)  d_in[2];
    const float* scales  = (const float*)d_in[3];
    const float* bias    = (const float*)d_in[4];
    float*       out     = (float*)d_out;

    gptq_fused_kernel<<<dim3(NTB, SPLIT), NTHREADS>>>(x, qweight, qzeros, scales, bias, out);
}